// round 14
// baseline (speedup 1.0000x reference)
#include <cuda_runtime.h>
#include <cstdint>

#define BSZ 8
#define LSEQ 1024
#define DMODEL 512
#define DINNER 1024
#define DSTATE 16
#define DTRANK 32
#define DCONV 4
#define ALPHA 0.2f
#define LN_EPS 1e-5f

// ---------------- scratch (static device globals; no allocation) ----------------
__device__ float g_t  [BSZ * LSEQ * DMODEL];      // residual stream (8,1024,512)
__device__ float g_ln [BSZ * LSEQ * DMODEL];      // layernormed input
__device__ float g_uz [BSZ * LSEQ * 2 * DINNER];  // [u | z] (8,1024,2048)
__device__ float g_uc [BSZ * LSEQ * DINNER];      // conv+silu output
__device__ float g_dbc[BSZ * LSEQ * 64];          // [dt_r(32) | B(16) | C(16)]
__device__ float g_dt [BSZ * LSEQ * DINNER];      // softplus(dt)
__device__ float g_y  [BSZ * LSEQ * DINNER];      // scan output * silu(z)

// ---------------- input embed: t = x(B,HW,3) @ W_inp + b_inp ----------------
__global__ void embed_kernel(const float* __restrict__ x,
                             const float* __restrict__ W_inp,
                             const float* __restrict__ b_inp) {
    int bl = blockIdx.x;            // 0..8191
    int d  = threadIdx.x;           // 0..511
    int b  = bl >> 10;
    int l  = bl & 1023;
    float acc = b_inp[d];
    #pragma unroll
    for (int c = 0; c < 3; c++)
        acc += x[((b * 3 + c) << 10) + l] * W_inp[c * DMODEL + d];
    g_t[bl * DMODEL + d] = acc;
}

// ---------------- layernorm over D=512, one block per row ----------------
__global__ void ln_kernel(const float* __restrict__ in, float* __restrict__ out,
                          const float* __restrict__ w, const float* __restrict__ bpar) {
    __shared__ float red[DMODEL];
    __shared__ float s_mu, s_var;
    int row = blockIdx.x;
    int d = threadIdx.x;
    float v = in[row * DMODEL + d];
    red[d] = v;
    __syncthreads();
    for (int s = DMODEL / 2; s > 0; s >>= 1) {
        if (d < s) red[d] += red[d + s];
        __syncthreads();
    }
    if (d == 0) s_mu = red[0] * (1.0f / DMODEL);
    __syncthreads();
    float diff = v - s_mu;
    red[d] = diff * diff;
    __syncthreads();
    for (int s = DMODEL / 2; s > 0; s >>= 1) {
        if (d < s) red[d] += red[d + s];
        __syncthreads();
    }
    if (d == 0) s_var = red[0] * (1.0f / DMODEL);
    __syncthreads();
    out[row * DMODEL + d] = diff * rsqrtf(s_var + LN_EPS) * w[d] + bpar[d];
}

// ---------------- generic fp32 GEMM: C[M,N] = A[M,K(lda)] @ B[K,N] (+bias)(+epi) ----
// tile 128x64, BK=16, 256 threads, 8x4 per thread. M=8192 always; M,N,K divisible.
// EPI: 0 = bias, 1 = bias+softplus, 2 = bias + residual add into C (in-place)
template <int EPI>
__global__ void gemm_kernel(const float* __restrict__ A, int lda,
                            const float* __restrict__ Bw,
                            const float* __restrict__ bias,
                            float* __restrict__ Cmat, int N, int K) {
    __shared__ float As[16][128];
    __shared__ float Bs[16][64];
    const int bm0 = blockIdx.y * 128;
    const int bn0 = blockIdx.x * 64;
    const int tx = threadIdx.x & 15;
    const int ty = threadIdx.x >> 4;

    float acc[8][4];
    #pragma unroll
    for (int i = 0; i < 8; i++)
        #pragma unroll
        for (int j = 0; j < 4; j++) acc[i][j] = 0.f;

    for (int kt = 0; kt < K; kt += 16) {
        // load A tile 128x16 (transposed into As[k][m]) : 2 float4 per thread
        #pragma unroll
        for (int i = 0; i < 2; i++) {
            int idx = threadIdx.x * 2 + i;   // 0..511
            int row = idx >> 2;              // 0..127
            int c4  = (idx & 3) * 4;         // 0,4,8,12
            float4 a = *(const float4*)&A[(bm0 + row) * lda + kt + c4];
            As[c4 + 0][row] = a.x;
            As[c4 + 1][row] = a.y;
            As[c4 + 2][row] = a.z;
            As[c4 + 3][row] = a.w;
        }
        // load B tile 16x64 : 1 float4 per thread
        {
            int krow = threadIdx.x >> 4;         // 0..15
            int nc   = (threadIdx.x & 15) * 4;   // 0..60
            *(float4*)&Bs[krow][nc] = *(const float4*)&Bw[(kt + krow) * N + bn0 + nc];
        }
        __syncthreads();
        #pragma unroll
        for (int k = 0; k < 16; k++) {
            float4 b4 = *(float4*)&Bs[k][tx * 4];
            float4 a0 = *(float4*)&As[k][ty * 8];
            float4 a1 = *(float4*)&As[k][ty * 8 + 4];
            float av[8] = {a0.x, a0.y, a0.z, a0.w, a1.x, a1.y, a1.z, a1.w};
            float bv[4] = {b4.x, b4.y, b4.z, b4.w};
            #pragma unroll
            for (int i = 0; i < 8; i++)
                #pragma unroll
                for (int j = 0; j < 4; j++) acc[i][j] += av[i] * bv[j];
        }
        __syncthreads();
    }

    float4 bb = make_float4(0.f, 0.f, 0.f, 0.f);
    if (bias) bb = *(const float4*)&bias[bn0 + tx * 4];

    #pragma unroll
    for (int i = 0; i < 8; i++) {
        int m = bm0 + ty * 8 + i;
        float* cp = &Cmat[m * N + bn0 + tx * 4];
        float4 v = make_float4(acc[i][0] + bb.x, acc[i][1] + bb.y,
                               acc[i][2] + bb.z, acc[i][3] + bb.w);
        if (EPI == 1) {  // softplus
            v.x = (v.x > 20.f) ? v.x : log1pf(__expf(v.x));
            v.y = (v.y > 20.f) ? v.y : log1pf(__expf(v.y));
            v.z = (v.z > 20.f) ? v.z : log1pf(__expf(v.z));
            v.w = (v.w > 20.f) ? v.w : log1pf(__expf(v.w));
        }
        if (EPI == 2) {  // residual add (in-place on Cmat)
            float4 old = *(float4*)cp;
            v.x += old.x; v.y += old.y; v.z += old.z; v.w += old.w;
        }
        *(float4*)cp = v;
    }
}

// ---------------- depthwise causal conv (width 4) + silu ----------------
__global__ void conv_silu_kernel(const float* __restrict__ cw,
                                 const float* __restrict__ cb) {
    int idx = blockIdx.x * blockDim.x + threadIdx.x;   // 0 .. 8*1024*1024-1
    int e = idx & 1023;
    int l = (idx >> 10) & 1023;
    int b = idx >> 20;
    float acc = cb[e];
    #pragma unroll
    for (int k = 0; k < DCONV; k++) {
        int ls = l - (DCONV - 1) + k;
        if (ls >= 0)
            acc += g_uz[(((b << 10) + ls) << 11) + e] * cw[e * DCONV + k];
    }
    // silu
    acc = acc / (1.f + __expf(-acc));
    g_uc[idx] = acc;
}

// ---------------- selective scan (Luenberger-corrected) ----------------
// one thread per (b,e); h[16] in registers; serial over L.
__global__ void scan_kernel(const float* __restrict__ A_log,
                            const float* __restrict__ D_skip) {
    int b = blockIdx.x >> 3;                              // 0..7
    int e = ((blockIdx.x & 7) << 7) + threadIdx.x;        // 0..1023
    float h[DSTATE];
    float Aa[DSTATE];
    #pragma unroll
    for (int n = 0; n < DSTATE; n++) {
        h[n] = 0.f;
        Aa[n] = -__expf(A_log[e * DSTATE + n]);
    }
    float Dv = D_skip[e];

    const float* dtp = g_dt + (b << 10) * DINNER + e;
    const float* ucp = g_uc + (b << 10) * DINNER + e;
    const float* zp  = g_uz + (b << 10) * (2 * DINNER) + DINNER + e;
    float* yp = g_y + (b << 10) * DINNER + e;

    for (int l = 0; l < LSEQ; l++) {
        float dt = dtp[l * DINNER];
        float u  = ucp[l * DINNER];
        float z  = zp[l * 2 * DINNER];
        const float4* bc = (const float4*)(g_dbc + (((b << 10) + l) << 6) + DTRANK);
        float4 B0 = bc[0], B1 = bc[1], B2 = bc[2], B3 = bc[3];
        float4 C0 = bc[4], C1 = bc[5], C2 = bc[6], C3 = bc[7];
        float Bv[16] = {B0.x, B0.y, B0.z, B0.w, B1.x, B1.y, B1.z, B1.w,
                        B2.x, B2.y, B2.z, B2.w, B3.x, B3.y, B3.z, B3.w};
        float Cv[16] = {C0.x, C0.y, C0.z, C0.w, C1.x, C1.y, C1.z, C1.w,
                        C2.x, C2.y, C2.z, C2.w, C3.x, C3.y, C3.z, C3.w};
        float dtu = dt * u;
        float dot = 0.f, c2 = 0.f;
        #pragma unroll
        for (int n = 0; n < DSTATE; n++) {
            float ea = __expf(dt * Aa[n]);
            h[n] = ea * h[n] + dtu * Bv[n];
            dot += h[n] * Cv[n];
            c2  += Cv[n] * Cv[n];
        }
        float err = u - dot;
        float ae = ALPHA * err;
        #pragma unroll
        for (int n = 0; n < DSTATE; n++) h[n] += ae * Cv[n];
        float y = dot + ae * c2 + Dv * u;
        float zs = z / (1.f + __expf(-z));
        yp[l * DINNER] = y * zs;
    }
}

// ---------------- head: mean over L, layernorm, classifier ----------------
__global__ void head_kernel(const float* __restrict__ lnf_w,
                            const float* __restrict__ lnf_b,
                            const float* __restrict__ W_cls,
                            const float* __restrict__ b_cls,
                            float* __restrict__ out) {
    __shared__ float red[DMODEL];
    __shared__ float vec[DMODEL];
    __shared__ float s_mu, s_var;
    int b = blockIdx.x;
    int d = threadIdx.x;
    float s = 0.f;
    for (int l = 0; l < LSEQ; l++)
        s += g_t[(((b << 10) + l) * DMODEL) + d];
    float mean = s * (1.0f / LSEQ);
    red[d] = mean;
    __syncthreads();
    for (int st = DMODEL / 2; st > 0; st >>= 1) {
        if (d < st) red[d] += red[d + st];
        __syncthreads();
    }
    if (d == 0) s_mu = red[0] * (1.0f / DMODEL);
    __syncthreads();
    float diff = mean - s_mu;
    red[d] = diff * diff;
    __syncthreads();
    for (int st = DMODEL / 2; st > 0; st >>= 1) {
        if (d < st) red[d] += red[d + st];
        __syncthreads();
    }
    if (d == 0) s_var = red[0] * (1.0f / DMODEL);
    __syncthreads();
    vec[d] = diff * rsqrtf(s_var + LN_EPS) * lnf_w[d] + lnf_b[d];
    __syncthreads();
    if (d < 10) {
        float acc = b_cls[d];
        for (int k = 0; k < DMODEL; k++)
            acc += vec[k] * W_cls[k * 10 + d];
        out[b * 10 + d] = acc;
    }
}

// ---------------- host launch ----------------
extern "C" void kernel_launch(void* const* d_in, const int* in_sizes, int n_in,
                              void* d_out, int out_size) {
    const float* x      = (const float*)d_in[0];
    const float* W_inp  = (const float*)d_in[1];
    const float* b_inp  = (const float*)d_in[2];
    const float* W_in   = (const float*)d_in[3];
    const float* b_in   = (const float*)d_in[4];
    const float* conv_w = (const float*)d_in[5];
    const float* conv_b = (const float*)d_in[6];
    const float* W_x    = (const float*)d_in[7];
    const float* W_dt   = (const float*)d_in[8];
    const float* b_dt   = (const float*)d_in[9];
    const float* A_log  = (const float*)d_in[10];
    const float* D_skip = (const float*)d_in[11];
    const float* W_out  = (const float*)d_in[12];
    const float* b_out  = (const float*)d_in[13];
    const float* ln_w   = (const float*)d_in[14];
    const float* ln_b   = (const float*)d_in[15];
    const float* lnf_w  = (const float*)d_in[16];
    const float* lnf_b  = (const float*)d_in[17];
    const float* W_cls  = (const float*)d_in[18];
    const float* b_cls  = (const float*)d_in[19];

    float *p_t, *p_ln, *p_uz, *p_uc, *p_dbc, *p_dt, *p_y;
    cudaGetSymbolAddress((void**)&p_t,   g_t);
    cudaGetSymbolAddress((void**)&p_ln,  g_ln);
    cudaGetSymbolAddress((void**)&p_uz,  g_uz);
    cudaGetSymbolAddress((void**)&p_uc,  g_uc);
    cudaGetSymbolAddress((void**)&p_dbc, g_dbc);
    cudaGetSymbolAddress((void**)&p_dt,  g_dt);
    cudaGetSymbolAddress((void**)&p_y,   g_y);

    const int M = BSZ * LSEQ;  // 8192

    embed_kernel<<<M, DMODEL>>>(x, W_inp, b_inp);

    for (int i = 0; i < 4; i++) {
        ln_kernel<<<M, DMODEL>>>(p_t, p_ln, ln_w + i * DMODEL, ln_b + i * DMODEL);

        // uz = ln @ W_in + b_in   (8192,512)@(512,2048)
        gemm_kernel<0><<<dim3(2 * DINNER / 64, M / 128), 256>>>(
            p_ln, DMODEL, W_in + (size_t)i * DMODEL * 2 * DINNER,
            b_in + i * 2 * DINNER, p_uz, 2 * DINNER, DMODEL);

        conv_silu_kernel<<<(BSZ * LSEQ * DINNER) / 256, 256>>>(
            conv_w + i * DINNER * DCONV, conv_b + i * DINNER);

        // dbc = uc @ W_x          (8192,1024)@(1024,64)
        gemm_kernel<0><<<dim3(1, M / 128), 256>>>(
            p_uc, DINNER, W_x + (size_t)i * DINNER * 64,
            (const float*)nullptr, p_dbc, 64, DINNER);

        // dt = softplus(dbc[:,:32] @ W_dt + b_dt)   (8192,32)@(32,1024)
        gemm_kernel<1><<<dim3(DINNER / 64, M / 128), 256>>>(
            p_dbc, 64, W_dt + (size_t)i * DTRANK * DINNER,
            b_dt + i * DINNER, p_dt, DINNER, DTRANK);

        scan_kernel<<<64, 128>>>(A_log + (size_t)i * DINNER * DSTATE,
                                 D_skip + i * DINNER);

        // t += y @ W_out + b_out  (8192,1024)@(1024,512), residual epilogue
        gemm_kernel<2><<<dim3(DMODEL / 64, M / 128), 256>>>(
            p_y, DINNER, W_out + (size_t)i * DINNER * DMODEL,
            b_out + i * DMODEL, p_t, DMODEL, DINNER);
    }

    head_kernel<<<BSZ, DMODEL>>>(lnf_w, lnf_b, W_cls, b_cls, (float*)d_out);
}

// round 15
// speedup vs baseline: 1.0240x; 1.0240x over previous
#include <cuda_runtime.h>
#include <cstdint>

#define BSZ 8
#define LSEQ 1024
#define DMODEL 512
#define DINNER 1024
#define DSTATE 16
#define DTRANK 32
#define DCONV 4
#define ALPHA 0.2f
#define LN_EPS 1e-5f

// ---------------- scratch (static device globals; no allocation) ----------------
__device__ float g_t  [BSZ * LSEQ * DMODEL];      // residual stream (8,1024,512)
__device__ float g_ln [BSZ * LSEQ * DMODEL];      // layernormed input
__device__ float g_uz [BSZ * LSEQ * 2 * DINNER];  // [u | z] (8,1024,2048)
__device__ float g_uc [BSZ * LSEQ * DINNER];      // conv+silu output
__device__ float g_dbc[BSZ * LSEQ * 64];          // [dt_r(32) | B(16) | C(16)]
__device__ float g_dt [BSZ * LSEQ * DINNER];      // softplus(dt)
__device__ float g_y  [BSZ * LSEQ * DINNER];      // scan output * silu(z)

// ---------------- input embed: t = x(B,HW,3) @ W_inp + b_inp ----------------
__global__ void embed_kernel(const float* __restrict__ x,
                             const float* __restrict__ W_inp,
                             const float* __restrict__ b_inp) {
    int bl = blockIdx.x;            // 0..8191
    int d  = threadIdx.x;           // 0..511
    int b  = bl >> 10;
    int l  = bl & 1023;
    float acc = b_inp[d];
    #pragma unroll
    for (int c = 0; c < 3; c++)
        acc += x[((b * 3 + c) << 10) + l] * W_inp[c * DMODEL + d];
    g_t[bl * DMODEL + d] = acc;
}

// ---------------- layernorm over D=512, one block per row ----------------
__global__ void ln_kernel(const float* __restrict__ in, float* __restrict__ out,
                          const float* __restrict__ w, const float* __restrict__ bpar) {
    __shared__ float red[DMODEL];
    __shared__ float s_mu, s_var;
    int row = blockIdx.x;
    int d = threadIdx.x;
    float v = in[row * DMODEL + d];
    red[d] = v;
    __syncthreads();
    for (int s = DMODEL / 2; s > 0; s >>= 1) {
        if (d < s) red[d] += red[d + s];
        __syncthreads();
    }
    if (d == 0) s_mu = red[0] * (1.0f / DMODEL);
    __syncthreads();
    float diff = v - s_mu;
    red[d] = diff * diff;
    __syncthreads();
    for (int s = DMODEL / 2; s > 0; s >>= 1) {
        if (d < s) red[d] += red[d + s];
        __syncthreads();
    }
    if (d == 0) s_var = red[0] * (1.0f / DMODEL);
    __syncthreads();
    out[row * DMODEL + d] = diff * rsqrtf(s_var + LN_EPS) * w[d] + bpar[d];
}

// ---------------- generic fp32 GEMM: C[M,N] = A[M,K(lda)] @ B[K,N] (+bias)(+epi) ----
// tile 128x64, BK=16, 256 threads, 8x4 per thread. M=8192 always; M,N,K divisible.
// EPI: 0 = bias, 1 = bias+softplus, 2 = bias + residual add into C (in-place)
template <int EPI>
__global__ void gemm_kernel(const float* __restrict__ A, int lda,
                            const float* __restrict__ Bw,
                            const float* __restrict__ bias,
                            float* __restrict__ Cmat, int N, int K) {
    __shared__ float As[16][128];
    __shared__ float Bs[16][64];
    const int bm0 = blockIdx.y * 128;
    const int bn0 = blockIdx.x * 64;
    const int tx = threadIdx.x & 15;
    const int ty = threadIdx.x >> 4;

    float acc[8][4];
    #pragma unroll
    for (int i = 0; i < 8; i++)
        #pragma unroll
        for (int j = 0; j < 4; j++) acc[i][j] = 0.f;

    for (int kt = 0; kt < K; kt += 16) {
        // load A tile 128x16 (transposed into As[k][m]) : 2 float4 per thread
        #pragma unroll
        for (int i = 0; i < 2; i++) {
            int idx = threadIdx.x * 2 + i;   // 0..511
            int row = idx >> 2;              // 0..127
            int c4  = (idx & 3) * 4;         // 0,4,8,12
            float4 a = *(const float4*)&A[(bm0 + row) * lda + kt + c4];
            As[c4 + 0][row] = a.x;
            As[c4 + 1][row] = a.y;
            As[c4 + 2][row] = a.z;
            As[c4 + 3][row] = a.w;
        }
        // load B tile 16x64 : 1 float4 per thread
        {
            int krow = threadIdx.x >> 4;         // 0..15
            int nc   = (threadIdx.x & 15) * 4;   // 0..60
            *(float4*)&Bs[krow][nc] = *(const float4*)&Bw[(kt + krow) * N + bn0 + nc];
        }
        __syncthreads();
        #pragma unroll
        for (int k = 0; k < 16; k++) {
            float4 b4 = *(float4*)&Bs[k][tx * 4];
            float4 a0 = *(float4*)&As[k][ty * 8];
            float4 a1 = *(float4*)&As[k][ty * 8 + 4];
            float av[8] = {a0.x, a0.y, a0.z, a0.w, a1.x, a1.y, a1.z, a1.w};
            float bv[4] = {b4.x, b4.y, b4.z, b4.w};
            #pragma unroll
            for (int i = 0; i < 8; i++)
                #pragma unroll
                for (int j = 0; j < 4; j++) acc[i][j] += av[i] * bv[j];
        }
        __syncthreads();
    }

    float4 bb = make_float4(0.f, 0.f, 0.f, 0.f);
    if (bias) bb = *(const float4*)&bias[bn0 + tx * 4];

    #pragma unroll
    for (int i = 0; i < 8; i++) {
        int m = bm0 + ty * 8 + i;
        float* cp = &Cmat[m * N + bn0 + tx * 4];
        float4 v = make_float4(acc[i][0] + bb.x, acc[i][1] + bb.y,
                               acc[i][2] + bb.z, acc[i][3] + bb.w);
        if (EPI == 1) {  // softplus
            v.x = (v.x > 20.f) ? v.x : log1pf(__expf(v.x));
            v.y = (v.y > 20.f) ? v.y : log1pf(__expf(v.y));
            v.z = (v.z > 20.f) ? v.z : log1pf(__expf(v.z));
            v.w = (v.w > 20.f) ? v.w : log1pf(__expf(v.w));
        }
        if (EPI == 2) {  // residual add (in-place on Cmat)
            float4 old = *(float4*)cp;
            v.x += old.x; v.y += old.y; v.z += old.z; v.w += old.w;
        }
        *(float4*)cp = v;
    }
}

// ---------------- depthwise causal conv (width 4) + silu ----------------
__global__ void conv_silu_kernel(const float* __restrict__ cw,
                                 const float* __restrict__ cb) {
    int idx = blockIdx.x * blockDim.x + threadIdx.x;   // 0 .. 8*1024*1024-1
    int e = idx & 1023;
    int l = (idx >> 10) & 1023;
    int b = idx >> 20;
    float acc = cb[e];
    #pragma unroll
    for (int k = 0; k < DCONV; k++) {
        int ls = l - (DCONV - 1) + k;
        if (ls >= 0)
            acc += g_uz[(((b << 10) + ls) << 11) + e] * cw[e * DCONV + k];
    }
    // silu
    acc = acc / (1.f + __expf(-acc));
    g_uc[idx] = acc;
}

// ---------------- selective scan (Luenberger-corrected) ----------------
// one thread per (b,e); h[16] in registers; serial over L.
__global__ void scan_kernel(const float* __restrict__ A_log,
                            const float* __restrict__ D_skip) {
    int b = blockIdx.x >> 3;                              // 0..7
    int e = ((blockIdx.x & 7) << 7) + threadIdx.x;        // 0..1023
    float h[DSTATE];
    float Aa[DSTATE];
    #pragma unroll
    for (int n = 0; n < DSTATE; n++) {
        h[n] = 0.f;
        Aa[n] = -__expf(A_log[e * DSTATE + n]);
    }
    float Dv = D_skip[e];

    const float* dtp = g_dt + (b << 10) * DINNER + e;
    const float* ucp = g_uc + (b << 10) * DINNER + e;
    const float* zp  = g_uz + (b << 10) * (2 * DINNER) + DINNER + e;
    float* yp = g_y + (b << 10) * DINNER + e;

    for (int l = 0; l < LSEQ; l++) {
        float dt = dtp[l * DINNER];
        float u  = ucp[l * DINNER];
        float z  = zp[l * 2 * DINNER];
        const float4* bc = (const float4*)(g_dbc + (((b << 10) + l) << 6) + DTRANK);
        float4 B0 = bc[0], B1 = bc[1], B2 = bc[2], B3 = bc[3];
        float4 C0 = bc[4], C1 = bc[5], C2 = bc[6], C3 = bc[7];
        float Bv[16] = {B0.x, B0.y, B0.z, B0.w, B1.x, B1.y, B1.z, B1.w,
                        B2.x, B2.y, B2.z, B2.w, B3.x, B3.y, B3.z, B3.w};
        float Cv[16] = {C0.x, C0.y, C0.z, C0.w, C1.x, C1.y, C1.z, C1.w,
                        C2.x, C2.y, C2.z, C2.w, C3.x, C3.y, C3.z, C3.w};
        float dtu = dt * u;
        float dot = 0.f, c2 = 0.f;
        #pragma unroll
        for (int n = 0; n < DSTATE; n++) {
            float ea = __expf(dt * Aa[n]);
            h[n] = ea * h[n] + dtu * Bv[n];
            dot += h[n] * Cv[n];
            c2  += Cv[n] * Cv[n];
        }
        float err = u - dot;
        float ae = ALPHA * err;
        #pragma unroll
        for (int n = 0; n < DSTATE; n++) h[n] += ae * Cv[n];
        float y = dot + ae * c2 + Dv * u;
        float zs = z / (1.f + __expf(-z));
        yp[l * DINNER] = y * zs;
    }
}

// ---------------- head: mean over L, layernorm, classifier ----------------
__global__ void head_kernel(const float* __restrict__ lnf_w,
                            const float* __restrict__ lnf_b,
                            const float* __restrict__ W_cls,
                            const float* __restrict__ b_cls,
                            float* __restrict__ out) {
    __shared__ float red[DMODEL];
    __shared__ float vec[DMODEL];
    __shared__ float s_mu, s_var;
    int b = blockIdx.x;
    int d = threadIdx.x;
    float s = 0.f;
    for (int l = 0; l < LSEQ; l++)
        s += g_t[(((b << 10) + l) * DMODEL) + d];
    float mean = s * (1.0f / LSEQ);
    red[d] = mean;
    __syncthreads();
    for (int st = DMODEL / 2; st > 0; st >>= 1) {
        if (d < st) red[d] += red[d + st];
        __syncthreads();
    }
    if (d == 0) s_mu = red[0] * (1.0f / DMODEL);
    __syncthreads();
    float diff = mean - s_mu;
    red[d] = diff * diff;
    __syncthreads();
    for (int st = DMODEL / 2; st > 0; st >>= 1) {
        if (d < st) red[d] += red[d + st];
        __syncthreads();
    }
    if (d == 0) s_var = red[0] * (1.0f / DMODEL);
    __syncthreads();
    vec[d] = diff * rsqrtf(s_var + LN_EPS) * lnf_w[d] + lnf_b[d];
    __syncthreads();
    if (d < 10) {
        float acc = b_cls[d];
        for (int k = 0; k < DMODEL; k++)
            acc += vec[k] * W_cls[k * 10 + d];
        out[b * 10 + d] = acc;
    }
}

// ---------------- host launch ----------------
extern "C" void kernel_launch(void* const* d_in, const int* in_sizes, int n_in,
                              void* d_out, int out_size) {
    const float* x      = (const float*)d_in[0];
    const float* W_inp  = (const float*)d_in[1];
    const float* b_inp  = (const float*)d_in[2];
    const float* W_in   = (const float*)d_in[3];
    const float* b_in   = (const float*)d_in[4];
    const float* conv_w = (const float*)d_in[5];
    const float* conv_b = (const float*)d_in[6];
    const float* W_x    = (const float*)d_in[7];
    const float* W_dt   = (const float*)d_in[8];
    const float* b_dt   = (const float*)d_in[9];
    const float* A_log  = (const float*)d_in[10];
    const float* D_skip = (const float*)d_in[11];
    const float* W_out  = (const float*)d_in[12];
    const float* b_out  = (const float*)d_in[13];
    const float* ln_w   = (const float*)d_in[14];
    const float* ln_b   = (const float*)d_in[15];
    const float* lnf_w  = (const float*)d_in[16];
    const float* lnf_b  = (const float*)d_in[17];
    const float* W_cls  = (const float*)d_in[18];
    const float* b_cls  = (const float*)d_in[19];

    float *p_t, *p_ln, *p_uz, *p_uc, *p_dbc, *p_dt, *p_y;
    cudaGetSymbolAddress((void**)&p_t,   g_t);
    cudaGetSymbolAddress((void**)&p_ln,  g_ln);
    cudaGetSymbolAddress((void**)&p_uz,  g_uz);
    cudaGetSymbolAddress((void**)&p_uc,  g_uc);
    cudaGetSymbolAddress((void**)&p_dbc, g_dbc);
    cudaGetSymbolAddress((void**)&p_dt,  g_dt);
    cudaGetSymbolAddress((void**)&p_y,   g_y);

    const int M = BSZ * LSEQ;  // 8192

    embed_kernel<<<M, DMODEL>>>(x, W_inp, b_inp);

    for (int i = 0; i < 4; i++) {
        ln_kernel<<<M, DMODEL>>>(p_t, p_ln, ln_w + i * DMODEL, ln_b + i * DMODEL);

        // uz = ln @ W_in + b_in   (8192,512)@(512,2048)
        gemm_kernel<0><<<dim3(2 * DINNER / 64, M / 128), 256>>>(
            p_ln, DMODEL, W_in + (size_t)i * DMODEL * 2 * DINNER,
            b_in + i * 2 * DINNER, p_uz, 2 * DINNER, DMODEL);

        conv_silu_kernel<<<(BSZ * LSEQ * DINNER) / 256, 256>>>(
            conv_w + i * DINNER * DCONV, conv_b + i * DINNER);

        // dbc = uc @ W_x          (8192,1024)@(1024,64)
        gemm_kernel<0><<<dim3(1, M / 128), 256>>>(
            p_uc, DINNER, W_x + (size_t)i * DINNER * 64,
            (const float*)nullptr, p_dbc, 64, DINNER);

        // dt = softplus(dbc[:,:32] @ W_dt + b_dt)   (8192,32)@(32,1024)
        gemm_kernel<1><<<dim3(DINNER / 64, M / 128), 256>>>(
            p_dbc, 64, W_dt + (size_t)i * DTRANK * DINNER,
            b_dt + i * DINNER, p_dt, DINNER, DTRANK);

        scan_kernel<<<64, 128>>>(A_log + (size_t)i * DINNER * DSTATE,
                                 D_skip + i * DINNER);

        // t += y @ W_out + b_out  (8192,1024)@(1024,512), residual epilogue
        gemm_kernel<2><<<dim3(DMODEL / 64, M / 128), 256>>>(
            p_y, DINNER, W_out + (size_t)i * DINNER * DMODEL,
            b_out + i * DMODEL, p_t, DMODEL, DINNER);
    }

    head_kernel<<<BSZ, DMODEL>>>(lnf_w, lnf_b, W_cls, b_cls, (float*)d_out);
}